// round 11
// baseline (speedup 1.0000x reference)
#include <cuda_runtime.h>
#include <cstdint>
#include <cstddef>

// Problem dims
#define SEQ  4096
#define EMB  512
#define HID  512
#define G4   2048            // 4*HID
#define NCTA 64              // scan CTAs (each owns 8 h-indices)
#define HPC  8               // h indices per CTA
#define STHREADS 256

// ---------------- device scratch (no allocs allowed) ----------------
__device__ float    g_gx[(size_t)SEQ * G4];   // 32 MB precomputed input gates
__device__ float    g_h[2][HID];              // double-buffered hidden state
__device__ unsigned g_counter;                // global step barrier counter

// ---------------- init: reset barrier + h0 every launch ----------------
__global__ void init_kernel() {
    int t = threadIdx.x;
    if (t < HID) { g_h[0][t] = 0.f; g_h[1][t] = 0.f; }
    if (t == 0) g_counter = 0u;
}

// ---------------- Phase A: gx[m][n] = emb[tokens[m]] . W_ih[n] + b_ih[n] + b_hh[n]
// 64x64 tile, K-chunks of 32, k-major smem tiles, fused gather.
__global__ __launch_bounds__(256) void gemm_kernel(
    const int*   __restrict__ tokens,
    const float* __restrict__ emb,
    const float* __restrict__ W_ih,
    const float* __restrict__ b_ih,
    const float* __restrict__ b_hh)
{
    __shared__ float As[32][64];   // [k][m]
    __shared__ float Bs[32][64];   // [k][n]

    const int m0 = blockIdx.y * 64;
    const int n0 = blockIdx.x * 64;
    const int tid  = threadIdx.x;
    const int lrow = tid >> 3;          // 0..31
    const int kq   = (tid & 7) * 4;     // 0,4,...,28
    const int tx   = tid & 15;          // 0..15 -> n micro
    const int ty   = tid >> 4;          // 0..15 -> m micro

    // gather row bases (fused embedding lookup)
    const int tok0 = __ldg(&tokens[m0 + lrow]);
    const int tok1 = __ldg(&tokens[m0 + lrow + 32]);
    const float* a0 = emb + (size_t)tok0 * EMB + kq;
    const float* a1 = emb + (size_t)tok1 * EMB + kq;
    const float* b0 = W_ih + (size_t)(n0 + lrow)      * EMB + kq;
    const float* b1 = W_ih + (size_t)(n0 + lrow + 32) * EMB + kq;

    float acc[4][4];
    #pragma unroll
    for (int i = 0; i < 4; i++)
        #pragma unroll
        for (int j = 0; j < 4; j++) acc[i][j] = 0.f;

    for (int k0 = 0; k0 < EMB; k0 += 32) {
        float4 va0 = *(const float4*)(a0 + k0);
        float4 va1 = *(const float4*)(a1 + k0);
        float4 vb0 = *(const float4*)(b0 + k0);
        float4 vb1 = *(const float4*)(b1 + k0);
        __syncthreads();  // previous chunk's compute done
        As[kq+0][lrow] = va0.x; As[kq+1][lrow] = va0.y;
        As[kq+2][lrow] = va0.z; As[kq+3][lrow] = va0.w;
        As[kq+0][lrow+32] = va1.x; As[kq+1][lrow+32] = va1.y;
        As[kq+2][lrow+32] = va1.z; As[kq+3][lrow+32] = va1.w;
        Bs[kq+0][lrow] = vb0.x; Bs[kq+1][lrow] = vb0.y;
        Bs[kq+2][lrow] = vb0.z; Bs[kq+3][lrow] = vb0.w;
        Bs[kq+0][lrow+32] = vb1.x; Bs[kq+1][lrow+32] = vb1.y;
        Bs[kq+2][lrow+32] = vb1.z; Bs[kq+3][lrow+32] = vb1.w;
        __syncthreads();
        #pragma unroll
        for (int k = 0; k < 32; k++) {
            float4 av = *(const float4*)&As[k][ty * 4];
            float4 bv = *(const float4*)&Bs[k][tx * 4];
            float a[4] = {av.x, av.y, av.z, av.w};
            float b[4] = {bv.x, bv.y, bv.z, bv.w};
            #pragma unroll
            for (int i = 0; i < 4; i++)
                #pragma unroll
                for (int j = 0; j < 4; j++)
                    acc[i][j] = fmaf(a[i], b[j], acc[i][j]);
        }
    }

    // epilogue with fused bias
    float bias[4];
    #pragma unroll
    for (int j = 0; j < 4; j++) {
        int n = n0 + tx * 4 + j;
        bias[j] = __ldg(&b_ih[n]) + __ldg(&b_hh[n]);
    }
    #pragma unroll
    for (int i = 0; i < 4; i++) {
        int m = m0 + ty * 4 + i;
        float4 o;
        o.x = acc[i][0] + bias[0];
        o.y = acc[i][1] + bias[1];
        o.z = acc[i][2] + bias[2];
        o.w = acc[i][3] + bias[3];
        *(float4*)&g_gx[(size_t)m * G4 + n0 + tx * 4] = o;
    }
}

// ---------------- Phase B: persistent sequential LSTM scan ----------------
// 64 CTAs x 256 threads. CTA b owns h-indices [8b, 8b+8).
// Thread t: row_local = t/8 (32 gate rows: gate = rl/8, jj = rl%8), seg = t%8
// owns 64 columns of W_hh in registers.
__device__ __forceinline__ float sigmoidf_(float x) {
    return 1.f / (1.f + expf(-x));
}

__global__ __launch_bounds__(STHREADS) void scan_kernel(
    const float* __restrict__ W_hh, float* __restrict__ out)
{
    __shared__ float hs[HID];
    __shared__ float gsum[32];

    const int tid  = threadIdx.x;
    const int base = blockIdx.x * HPC;
    const int row_local = tid >> 3;          // 0..31
    const int seg  = tid & 7;                // 0..7 -> columns seg*64..+63
    const int gate = row_local >> 3;         // 0..3 (i,f,g,o)
    const int jj   = row_local & 7;          // h index within CTA
    const int grow = gate * HID + base + jj; // global gate row

    // weights pinned in registers
    float w[64];
    const float* wr = W_hh + (size_t)grow * HID + seg * 64;
    #pragma unroll
    for (int i = 0; i < 64; i++) w[i] = wr[i];

    float cc = 0.f;     // cell state (valid on tid < 8)
    float hlast = 0.f;  // last hidden (valid on tid < 8)
    unsigned* cnt = &g_counter;

    for (int step = 0; step < SEQ; ++step) {
        // prefetch this step's input-gate value (independent of barrier)
        float gxv = __ldg(&g_gx[(size_t)step * G4 + grow]);

        if (step > 0) {
            if (tid == 0) {
                unsigned target = (unsigned)NCTA * (unsigned)step;
                unsigned v;
                do {
                    asm volatile("ld.acquire.gpu.b32 %0, [%1];"
                                 : "=r"(v) : "l"(cnt) : "memory");
                } while (v < target);
            }
            __syncthreads();
        }

        // reload full h from global (L2, bypass L1 to avoid staleness)
        const float* hsrc = g_h[step & 1];
        hs[tid]       = __ldcg(hsrc + tid);
        hs[tid + 256] = __ldcg(hsrc + tid + 256);
        __syncthreads();

        // partial dot over this thread's 64 columns
        float a0 = (seg == 0) ? gxv : 0.f;
        float a1 = 0.f, a2 = 0.f, a3 = 0.f;
        const float* hp = hs + seg * 64;
        #pragma unroll
        for (int i = 0; i < 64; i += 4) {
            float4 hv = *(const float4*)(hp + i);
            a0 = fmaf(w[i + 0], hv.x, a0);
            a1 = fmaf(w[i + 1], hv.y, a1);
            a2 = fmaf(w[i + 2], hv.z, a2);
            a3 = fmaf(w[i + 3], hv.w, a3);
        }
        float acc = (a0 + a1) + (a2 + a3);
        // reduce across the 8 segs (contiguous lanes)
        acc += __shfl_xor_sync(0xffffffffu, acc, 1);
        acc += __shfl_xor_sync(0xffffffffu, acc, 2);
        acc += __shfl_xor_sync(0xffffffffu, acc, 4);
        if (seg == 0) gsum[row_local] = acc;
        __syncthreads();

        if (tid < HPC) {
            float iv = sigmoidf_(gsum[tid]);
            float fv = sigmoidf_(gsum[8  + tid]);
            float gv = tanhf    (gsum[16 + tid]);
            float ov = sigmoidf_(gsum[24 + tid]);
            cc = fmaf(fv, cc, iv * gv);
            hlast = ov * tanhf(cc);
            g_h[(step + 1) & 1][base + tid] = hlast;
        }
        __syncthreads();  // order the h STGs before the release-arrive
        if (tid == 0) {
            asm volatile("red.release.gpu.add.u32 [%0], %1;"
                         :: "l"(cnt), "r"(1u) : "memory");
        }
    }

    if (tid < HPC) {
        out[base + tid]       = hlast;  // h
        out[HID + base + tid] = cc;     // c
    }
}

// ---------------- entry point ----------------
extern "C" void kernel_launch(void* const* d_in, const int* in_sizes, int n_in,
                              void* d_out, int out_size) {
    const int*   tokens = (const int*)  d_in[0];
    const float* emb    = (const float*)d_in[1];
    const float* W_ih   = (const float*)d_in[2];
    const float* W_hh   = (const float*)d_in[3];
    const float* b_ih   = (const float*)d_in[4];
    const float* b_hh   = (const float*)d_in[5];
    float* out = (float*)d_out;

    init_kernel<<<1, 512>>>();
    dim3 ggrid(G4 / 64, SEQ / 64);   // (32, 64)
    gemm_kernel<<<ggrid, 256>>>(tokens, emb, W_ih, b_ih, b_hh);
    scan_kernel<<<NCTA, STHREADS>>>(W_hh, out);
}

// round 17
// speedup vs baseline: 3.0729x; 3.0729x over previous
#include <cuda_runtime.h>
#include <cstdint>
#include <cstddef>

// Problem dims
#define SEQ  4096
#define EMB  512
#define HID  512
#define G4   2048            // 4*HID
#define NCTA 128             // scan CTAs (each owns 4 h-indices)
#define HPC  4               // h indices per CTA
#define STHREADS 256

// ---------------- device scratch (no allocs allowed) ----------------
__device__ float g_gx[(size_t)SEQ * G4];            // 32 MB precomputed input gates
__device__ unsigned long long g_hp[2][HID];         // double-buffered (tag<<32 | h bits)

// ---------------- init: tag buffers each launch ----------------
// buf0 = (tag=0, h=0.0f) -> h0 consumed at step 0.
// buf1 = never-match sentinel tag (expected tags there are odd, 1..4095).
__global__ void init_kernel() {
    int t = threadIdx.x;             // 512 threads
    if (blockIdx.x == 0) g_hp[0][t] = 0ull;
    else                 g_hp[1][t] = 0xFFFFFFFF00000000ull;
}

// ---------------- Phase A: gx[m][n] = emb[tokens[m]] . W_ih[n] + b_ih[n] + b_hh[n]
// (identical to the R11 kernel that passed)
__global__ __launch_bounds__(256) void gemm_kernel(
    const int*   __restrict__ tokens,
    const float* __restrict__ emb,
    const float* __restrict__ W_ih,
    const float* __restrict__ b_ih,
    const float* __restrict__ b_hh)
{
    __shared__ float As[32][64];   // [k][m]
    __shared__ float Bs[32][64];   // [k][n]

    const int m0 = blockIdx.y * 64;
    const int n0 = blockIdx.x * 64;
    const int tid  = threadIdx.x;
    const int lrow = tid >> 3;          // 0..31
    const int kq   = (tid & 7) * 4;     // 0,4,...,28
    const int tx   = tid & 15;          // 0..15 -> n micro
    const int ty   = tid >> 4;          // 0..15 -> m micro

    const int tok0 = __ldg(&tokens[m0 + lrow]);
    const int tok1 = __ldg(&tokens[m0 + lrow + 32]);
    const float* a0 = emb + (size_t)tok0 * EMB + kq;
    const float* a1 = emb + (size_t)tok1 * EMB + kq;
    const float* b0 = W_ih + (size_t)(n0 + lrow)      * EMB + kq;
    const float* b1 = W_ih + (size_t)(n0 + lrow + 32) * EMB + kq;

    float acc[4][4];
    #pragma unroll
    for (int i = 0; i < 4; i++)
        #pragma unroll
        for (int j = 0; j < 4; j++) acc[i][j] = 0.f;

    for (int k0 = 0; k0 < EMB; k0 += 32) {
        float4 va0 = *(const float4*)(a0 + k0);
        float4 va1 = *(const float4*)(a1 + k0);
        float4 vb0 = *(const float4*)(b0 + k0);
        float4 vb1 = *(const float4*)(b1 + k0);
        __syncthreads();
        As[kq+0][lrow] = va0.x; As[kq+1][lrow] = va0.y;
        As[kq+2][lrow] = va0.z; As[kq+3][lrow] = va0.w;
        As[kq+0][lrow+32] = va1.x; As[kq+1][lrow+32] = va1.y;
        As[kq+2][lrow+32] = va1.z; As[kq+3][lrow+32] = va1.w;
        Bs[kq+0][lrow] = vb0.x; Bs[kq+1][lrow] = vb0.y;
        Bs[kq+2][lrow] = vb0.z; Bs[kq+3][lrow] = vb0.w;
        Bs[kq+0][lrow+32] = vb1.x; Bs[kq+1][lrow+32] = vb1.y;
        Bs[kq+2][lrow+32] = vb1.z; Bs[kq+3][lrow+32] = vb1.w;
        __syncthreads();
        #pragma unroll
        for (int k = 0; k < 32; k++) {
            float4 av = *(const float4*)&As[k][ty * 4];
            float4 bv = *(const float4*)&Bs[k][tx * 4];
            float a[4] = {av.x, av.y, av.z, av.w};
            float b[4] = {bv.x, bv.y, bv.z, bv.w};
            #pragma unroll
            for (int i = 0; i < 4; i++)
                #pragma unroll
                for (int j = 0; j < 4; j++)
                    acc[i][j] = fmaf(a[i], b[j], acc[i][j]);
        }
    }

    float bias[4];
    #pragma unroll
    for (int j = 0; j < 4; j++) {
        int n = n0 + tx * 4 + j;
        bias[j] = __ldg(&b_ih[n]) + __ldg(&b_hh[n]);
    }
    #pragma unroll
    for (int i = 0; i < 4; i++) {
        int m = m0 + ty * 4 + i;
        float4 o;
        o.x = acc[i][0] + bias[0];
        o.y = acc[i][1] + bias[1];
        o.z = acc[i][2] + bias[2];
        o.w = acc[i][3] + bias[3];
        *(float4*)&g_gx[(size_t)m * G4 + n0 + tx * 4] = o;
    }
}

// ---------------- Phase B: persistent sequential LSTM scan ----------------
// 128 CTAs x 256 threads. CTA b owns h-indices [4b, 4b+4) -> 16 gate rows.
// Thread t: row = t>>4 (gate = row>>2, jj = row&3), seg s = t&15.
// Thread owns cols { 4*(16k+s)+j : k=0..7, j=0..3 } -> conflict-free LDS.128.
//
// h handoff: (tag,value) fused in one 64-bit word. st/ld.relaxed.gpu.b64 are
// single-copy atomic and L2-coherent per the PTX memory model — no torn
// reads, no write-once assumptions, one L2 round trip per step.
__global__ __launch_bounds__(STHREADS) void scan_kernel(
    const float* __restrict__ W_hh, float* __restrict__ out)
{
    __shared__ float hs[HID];
    __shared__ float gsum[16];
    __shared__ float asum[16];

    const int tid  = threadIdx.x;
    const int base = blockIdx.x * HPC;
    const int row  = tid >> 4;           // 0..15
    const int s    = tid & 15;           // seg
    const int gate = row >> 2;
    const int jj   = row & 3;
    const int grow = gate * HID + base + jj;

    // weights pinned in registers, interleaved-column layout (conflict-free)
    float4 w[8];
    const float* wr = W_hh + (size_t)grow * HID;
    #pragma unroll
    for (int k = 0; k < 8; k++)
        w[k] = *(const float4*)(wr + 4 * (16 * k + s));

    float cc = 0.f;
    float hlast = 0.f;

    for (int step = 0; step < SEQ; ++step) {
        // prefetch this step's input-gate value (independent of handoff)
        float gxv = 0.f;
        if (s == 0) gxv = __ldg(&g_gx[(size_t)step * G4 + grow]);

        // consume h(step): each thread polls two (tag,value) words
        {
            const unsigned long long* src = &g_hp[step & 1][0];
            const unsigned tag = (unsigned)step;
            unsigned long long v0 = 0, v1 = 0;
            bool d0 = false, d1 = false;
            do {
                if (!d0) {
                    asm volatile("ld.relaxed.gpu.global.b64 %0, [%1];"
                                 : "=l"(v0) : "l"(src + tid) : "memory");
                    d0 = ((unsigned)(v0 >> 32) == tag);
                }
                if (!d1) {
                    asm volatile("ld.relaxed.gpu.global.b64 %0, [%1];"
                                 : "=l"(v1) : "l"(src + tid + 256) : "memory");
                    d1 = ((unsigned)(v1 >> 32) == tag);
                }
            } while (!(d0 && d1));
            hs[tid]       = __uint_as_float((unsigned)v0);
            hs[tid + 256] = __uint_as_float((unsigned)v1);
        }
        __syncthreads();   // (A) hs ready; also WAR-fences gsum from prev step

        // partial dot: 8 float4 chunks at 4*(16k+s), bank-conflict-free
        float a0 = gxv, a1 = 0.f, a2 = 0.f, a3 = 0.f;
        #pragma unroll
        for (int k = 0; k < 8; k++) {
            float4 hv = *(const float4*)&hs[4 * (16 * k + s)];
            a0 = fmaf(w[k].x, hv.x, a0);
            a1 = fmaf(w[k].y, hv.y, a1);
            a2 = fmaf(w[k].z, hv.z, a2);
            a3 = fmaf(w[k].w, hv.w, a3);
        }
        float acc = (a0 + a1) + (a2 + a3);
        // reduce across the 16 segs (contiguous lane groups)
        acc += __shfl_xor_sync(0xffffffffu, acc, 1);
        acc += __shfl_xor_sync(0xffffffffu, acc, 2);
        acc += __shfl_xor_sync(0xffffffffu, acc, 4);
        acc += __shfl_xor_sync(0xffffffffu, acc, 8);
        if (s == 0) gsum[row] = acc;
        __syncthreads();   // (B) gsum ready; WAR-fences hs for next step

        // activations: rows 0-3 = i, 4-7 = f, 8-11 = g(tanh), 12-15 = o
        // (R11-proven numeric forms: expf / tanhf)
        if (tid < 16) {
            float gv = gsum[tid];
            float r;
            if ((tid >> 2) == 2) r = tanhf(gv);
            else                 r = 1.0f / (1.0f + expf(-gv));
            asum[tid] = r;
            __syncwarp(0x0000ffffu);
        }
        if (tid < HPC) {
            float iv = asum[tid];
            float fv = asum[4 + tid];
            float gv = asum[8 + tid];
            float ov = asum[12 + tid];
            cc = fmaf(fv, cc, iv * gv);
            hlast = ov * tanhf(cc);
            unsigned long long p =
                ((unsigned long long)(unsigned)(step + 1) << 32) |
                (unsigned long long)__float_as_uint(hlast);
            asm volatile("st.relaxed.gpu.global.b64 [%0], %1;"
                         :: "l"(&g_hp[(step + 1) & 1][base + tid]), "l"(p)
                         : "memory");
        }
        // no trailing sync needed: all hs reads precede sync (B)
    }

    if (tid < HPC) {
        out[base + tid]       = hlast;  // h
        out[HID + base + tid] = cc;     // c
    }
}

// ---------------- entry point ----------------
extern "C" void kernel_launch(void* const* d_in, const int* in_sizes, int n_in,
                              void* d_out, int out_size) {
    const int*   tokens = (const int*)  d_in[0];
    const float* emb    = (const float*)d_in[1];
    const float* W_ih   = (const float*)d_in[2];
    const float* W_hh   = (const float*)d_in[3];
    const float* b_ih   = (const float*)d_in[4];
    const float* b_hh   = (const float*)d_in[5];
    float* out = (float*)d_out;

    init_kernel<<<2, 512>>>();
    dim3 ggrid(G4 / 64, SEQ / 64);   // (32, 64)
    gemm_kernel<<<ggrid, 256>>>(tokens, emb, W_ih, b_ih, b_hh);
    scan_kernel<<<NCTA, STHREADS>>>(W_hh, out);
}